// round 1
// baseline (speedup 1.0000x reference)
#include <cuda_runtime.h>

// ---------------------------------------------------------------------------
// Stacked LSTM (T=64 timesteps, L=64 layers, B=128, H=64) + per-t dense head.
// Wavefront pipelining: 128 persistent CTAs = 64 layers x 2 batch-halves.
// CTA (l,g) owns batch rows [g*64, g*64+64) of layer l. Dependencies are
// neighbor-only (layer l needs layer l-1's h at same t), handled by
// acquire/release flags in global memory. Weights live in SMEM for all 64 t.
// GEMM: fp32 via packed fma.rn.f32x2 (2x FFMA throughput on sm_103a).
// ---------------------------------------------------------------------------

#define TT 64
#define LL 64
#define BB 128
#define HH 64

// Staging: h output of every (layer, t) cell. Written once per run per slot,
// so no anti-dependence hazards. 128 MB static (sanctioned scratch).
__device__ __align__(16) float g_hstage[(size_t)LL * TT * BB * HH];
__device__ int   g_flags[LL * TT * 2];
__device__ float g_pred[BB * TT];

__device__ __forceinline__ float sigm(float v)   { return 1.f / (1.f + __expf(-v)); }
__device__ __forceinline__ float tanh_f(float v) { return 1.f - 2.f / (__expf(2.f * v) + 1.f); }

__device__ __forceinline__ unsigned long long pack2(float x, float y) {
    unsigned long long r;
    asm("mov.b64 %0, {%1,%2};" : "=l"(r) : "f"(x), "f"(y));
    return r;
}
__device__ __forceinline__ void unpack2(unsigned long long v, float& x, float& y) {
    asm("mov.b64 {%0,%1}, %2;" : "=f"(x), "=f"(y) : "l"(v));
}
#define FMA2(d, a, b, c) \
    asm("fma.rn.f32x2 %0, %1, %2, %3;" : "=l"(d) : "l"(a), "l"(b), "l"(c))

__global__ void __launch_bounds__(256, 1) lstm_wave(
    const float* __restrict__ x,  const float* __restrict__ W0,
    const float* __restrict__ b0, const float* __restrict__ Wl,
    const float* __restrict__ bl, const float* __restrict__ Wd,
    const float* __restrict__ bd)
{
    extern __shared__ float smem[];
    float* Wsm = smem;                  // [128][256] weights (layer0: 65 rows)
    float* Asm = Wsm + 128 * 256;       // [64][128]  A = [h_below | h_own] (l>=1)
                                        //            or [h_own | x]        (l==0)
    float* Csm = Asm + 64 * 128;        // [64][64]   cell state
    float* Bsm = Csm + 64 * 64;         // [256]      bias

    const int bx   = blockIdx.x;
    const int l    = bx >> 1;
    const int g    = bx & 1;
    const int tid  = threadIdx.x;
    const int lane = tid & 31;          // n-group: columns lane*2 + 64p (p=gate)
    const int mg   = tid >> 5;          // warp = m-group
    const int m0   = mg << 3;           // 8 rows per warp

    const int K    = (l == 0) ? 65 : 128;
    const int hcol = (l == 0) ? 0  : 64;

    // ---- load weights + bias into SMEM (once) ----
    if (l == 0) {
        // Reorder: Wsm rows 0..63 = W0 rows 1..64 (h part), row 64 = W0 row 0 (x).
        for (int idx = tid; idx < 65 * 256; idx += 256) {
            int k = idx >> 8, n = idx & 255;
            int src = (k < 64) ? (k + 1) : 0;
            Wsm[idx] = W0[src * 256 + n];
        }
        Bsm[tid] = b0[tid];
    } else {
        const float4* Wg = (const float4*)(Wl + (size_t)(l - 1) * 128 * 256);
        float4* Wp = (float4*)Wsm;
        for (int idx = tid; idx < 128 * 256 / 4; idx += 256) Wp[idx] = Wg[idx];
        Bsm[tid] = bl[(l - 1) * 256 + tid];
    }
    for (int idx = tid; idx < 64 * 128; idx += 256) Asm[idx] = 0.f;
    for (int idx = tid; idx < 64 * 64;  idx += 256) Csm[idx] = 0.f;
    __syncthreads();

    // Pre-pack bias pairs for this thread's gate columns (n = lane*2 + 64p).
    unsigned long long bias2[4];
#pragma unroll
    for (int p = 0; p < 4; ++p)
        bias2[p] = pack2(Bsm[p * 64 + lane * 2], Bsm[p * 64 + lane * 2 + 1]);

    for (int t = 0; t < TT; ++t) {
        // ---- stage inputs ----
        if (l == 0) {
            if (tid < 64) Asm[tid * 128 + 64] = x[(g * 64 + tid) * TT + t];
            __syncthreads();
        } else {
            if (tid == 0) {
                const int* fp = &g_flags[((l - 1) * TT + t) * 2 + g];
                int v;
                do {
                    asm volatile("ld.acquire.gpu.global.b32 %0, [%1];"
                                 : "=r"(v) : "l"(fp) : "memory");
                } while (v == 0);
            }
            __syncthreads();
            const float4* src = (const float4*)(g_hstage +
                ((size_t)((l - 1) * TT + t) * BB + g * 64) * HH);
#pragma unroll
            for (int r = 0; r < 4; ++r) {
                int idx = tid + r * 256;        // 1024 float4s = 64x64 floats
                float4 v = src[idx];
                int m  = idx >> 4;              // 16 float4 per 64-float row
                int k4 = idx & 15;
                *(float4*)&Asm[m * 128 + k4 * 4] = v;
            }
            __syncthreads();
        }

        // ---- GEMM: z[64][256] = A[64][K] @ W[K][256] + b ----
        unsigned long long acc[8][4];
#pragma unroll
        for (int i = 0; i < 8; ++i)
#pragma unroll
            for (int p = 0; p < 4; ++p) acc[i][p] = bias2[p];

        const float* Arow = Asm + m0 * 128;
#pragma unroll 4
        for (int k = 0; k < K; ++k) {
            const float* wr = Wsm + k * 256 + lane * 2;
            unsigned long long w0_ = *(const unsigned long long*)(wr);
            unsigned long long w1_ = *(const unsigned long long*)(wr + 64);
            unsigned long long w2_ = *(const unsigned long long*)(wr + 128);
            unsigned long long w3_ = *(const unsigned long long*)(wr + 192);
#pragma unroll
            for (int i = 0; i < 8; ++i) {
                float a = Arow[i * 128 + k];           // SMEM broadcast
                unsigned long long a2 = pack2(a, a);
                FMA2(acc[i][0], a2, w0_, acc[i][0]);
                FMA2(acc[i][1], a2, w1_, acc[i][1]);
                FMA2(acc[i][2], a2, w2_, acc[i][2]);
                FMA2(acc[i][3], a2, w3_, acc[i][3]);
            }
        }
        __syncthreads();   // all A reads done before h writes below

        // ---- gates: thread owns 2 h-units x 8 rows; pairs p = (i,j,f,o) ----
        float hx[8], hy[8];
#pragma unroll
        for (int i = 0; i < 8; ++i) {
            int m = m0 + i;
            float ix, iy, jx, jy, fx, fy, ox, oy;
            unpack2(acc[i][0], ix, iy);
            unpack2(acc[i][1], jx, jy);
            unpack2(acc[i][2], fx, fy);
            unpack2(acc[i][3], ox, oy);
            float2 c = *(float2*)&Csm[m * 64 + lane * 2];
            c.x = c.x * sigm(fx) + sigm(ix) * tanh_f(jx);
            c.y = c.y * sigm(fy) + sigm(iy) * tanh_f(jy);
            hx[i] = tanh_f(c.x) * sigm(ox);
            hy[i] = tanh_f(c.y) * sigm(oy);
            *(float2*)&Csm[m * 64 + lane * 2] = c;
            float2 h2 = make_float2(hx[i], hy[i]);
            *(float2*)&Asm[m * 128 + hcol + lane * 2] = h2;  // own h for t+1
        }

        if (l < 63) {
            // publish h to layer above, then release flag
            float* dst = g_hstage + ((size_t)(l * TT + t) * BB + g * 64) * HH;
#pragma unroll
            for (int i = 0; i < 8; ++i)
                *(float2*)&dst[(m0 + i) * 64 + lane * 2] = make_float2(hx[i], hy[i]);
            __threadfence();
            __syncthreads();
            if (tid == 0) {
                int* fp = &g_flags[(l * TT + t) * 2 + g];
                asm volatile("st.release.gpu.global.b32 [%0], %1;"
                             :: "l"(fp), "r"(1) : "memory");
            }
        } else {
            // dense head: pred[b,t] = relu(h . Wd[t] + bd[t])
            float wdx = __ldg(&Wd[t * 64 + lane * 2]);
            float wdy = __ldg(&Wd[t * 64 + lane * 2 + 1]);
            float bdt = __ldg(&bd[t]);
#pragma unroll
            for (int i = 0; i < 8; ++i) {
                float v = hx[i] * wdx + hy[i] * wdy;
#pragma unroll
                for (int off = 16; off; off >>= 1)
                    v += __shfl_xor_sync(0xffffffffu, v, off);
                if (lane == 0)
                    g_pred[(g * 64 + m0 + i) * TT + t] = fmaxf(v + bdt, 0.f);
            }
        }
    }
}

__global__ void reset_flags_kernel() {
    int i = blockIdx.x * blockDim.x + threadIdx.x;
    if (i < LL * TT * 2) g_flags[i] = 0;
}

__global__ void finish_kernel(const float* __restrict__ labels,
                              float* __restrict__ out, int out_size)
{
    __shared__ float red[256];
    int tid = threadIdx.x;
    bool write_pred = (out_size >= BB * TT);
    float s = 0.f;
    for (int i = tid; i < BB * TT; i += 256) {
        float p = g_pred[i];
        if (write_pred) out[i] = p;
        float d = labels[i] - p;
        s += d * d;
    }
    red[tid] = s;
    __syncthreads();
    for (int w = 128; w; w >>= 1) {
        if (tid < w) red[tid] += red[tid + w];
        __syncthreads();
    }
    if (tid == 0) {
        float loss = red[0] / (float)(BB * TT);
        if (out_size >= BB * TT + 1)      out[BB * TT] = loss;
        else if (out_size < BB * TT)      out[0] = loss;   // loss-only layout
    }
}

extern "C" void kernel_launch(void* const* d_in, const int* in_sizes, int n_in,
                              void* d_out, int out_size)
{
    const float* x      = (const float*)d_in[0];
    const float* labels = (const float*)d_in[1];
    const float* W0     = (const float*)d_in[2];
    const float* b0     = (const float*)d_in[3];
    const float* Wl     = (const float*)d_in[4];
    const float* bl     = (const float*)d_in[5];
    const float* Wd     = (const float*)d_in[6];
    const float* bd     = (const float*)d_in[7];
    float* out = (float*)d_out;

    size_t smem = (size_t)(128 * 256 + 64 * 128 + 64 * 64 + 256) * sizeof(float);
    cudaFuncSetAttribute(lstm_wave, cudaFuncAttributeMaxDynamicSharedMemorySize,
                         (int)smem);

    reset_flags_kernel<<<(LL * TT * 2 + 255) / 256, 256>>>();
    lstm_wave<<<LL * 2, 256, smem>>>(x, W0, b0, Wl, bl, Wd, bd);
    finish_kernel<<<1, 256>>>(labels, out, out_size);
}

// round 2
// speedup vs baseline: 1.0519x; 1.0519x over previous
#include <cuda_runtime.h>

// ---------------------------------------------------------------------------
// Stacked LSTM (T=64 timesteps, L=64 layers, B=128, H=64) + per-t dense head.
// Wavefront pipelining: 128 persistent CTAs = 64 layers x 2 batch-halves.
// CTA (l,g) owns batch rows [g*64, g*64+64) of layer l. Dependencies are
// neighbor-only (layer l needs layer l-1's h at same t), handled by
// acquire/release flags in global memory. Weights live in SMEM for all 64 t.
// GEMM: fp32 via packed fma.rn.f32x2 (2x FFMA throughput on sm_103a).
// ---------------------------------------------------------------------------

#define TT 64
#define LL 64
#define BB 128
#define HH 64

// Staging: h output of every (layer, t) cell. Written once per run per slot,
// so no anti-dependence hazards. 128 MB static (sanctioned scratch).
__device__ __align__(16) float g_hstage[(size_t)LL * TT * BB * HH];
__device__ int   g_flags[LL * TT * 2];
__device__ float g_pred[BB * TT];

__device__ __forceinline__ float sigm(float v)   { return 1.f / (1.f + __expf(-v)); }
__device__ __forceinline__ float tanh_f(float v) { return 1.f - 2.f / (__expf(2.f * v) + 1.f); }

__device__ __forceinline__ unsigned long long pack2(float x, float y) {
    unsigned long long r;
    asm("mov.b64 %0, {%1,%2};" : "=l"(r) : "f"(x), "f"(y));
    return r;
}
__device__ __forceinline__ void unpack2(unsigned long long v, float& x, float& y) {
    asm("mov.b64 {%0,%1}, %2;" : "=f"(x), "=f"(y) : "l"(v));
}
#define FMA2(d, a, b, c) \
    asm("fma.rn.f32x2 %0, %1, %2, %3;" : "=l"(d) : "l"(a), "l"(b), "l"(c))

__global__ void __launch_bounds__(256, 1) lstm_wave(
    const float* __restrict__ x,  const float* __restrict__ W0,
    const float* __restrict__ b0, const float* __restrict__ Wl,
    const float* __restrict__ bl, const float* __restrict__ Wd,
    const float* __restrict__ bd)
{
    extern __shared__ float smem[];
    float* Wsm = smem;                  // [128][256] weights (layer0: 65 rows)
    float* Asm = Wsm + 128 * 256;       // [64][128]  A = [h_below | h_own] (l>=1)
                                        //            or [h_own | x]        (l==0)
    float* Csm = Asm + 64 * 128;        // [64][64]   cell state
    float* Bsm = Csm + 64 * 64;         // [256]      bias

    const int bx   = blockIdx.x;
    const int l    = bx >> 1;
    const int g    = bx & 1;
    const int tid  = threadIdx.x;
    const int lane = tid & 31;          // n-group: columns lane*2 + 64p (p=gate)
    const int mg   = tid >> 5;          // warp = m-group
    const int m0   = mg << 3;           // 8 rows per warp

    const int K    = (l == 0) ? 65 : 128;
    const int hcol = (l == 0) ? 0  : 64;

    // ---- load weights + bias into SMEM (once) ----
    if (l == 0) {
        // Reorder: Wsm rows 0..63 = W0 rows 1..64 (h part), row 64 = W0 row 0 (x).
        for (int idx = tid; idx < 65 * 256; idx += 256) {
            int k = idx >> 8, n = idx & 255;
            int src = (k < 64) ? (k + 1) : 0;
            Wsm[idx] = W0[src * 256 + n];
        }
        Bsm[tid] = b0[tid];
    } else {
        const float4* Wg = (const float4*)(Wl + (size_t)(l - 1) * 128 * 256);
        float4* Wp = (float4*)Wsm;
        for (int idx = tid; idx < 128 * 256 / 4; idx += 256) Wp[idx] = Wg[idx];
        Bsm[tid] = bl[(l - 1) * 256 + tid];
    }
    for (int idx = tid; idx < 64 * 128; idx += 256) Asm[idx] = 0.f;
    for (int idx = tid; idx < 64 * 64;  idx += 256) Csm[idx] = 0.f;
    __syncthreads();

    // Pre-pack bias pairs for this thread's gate columns (n = lane*2 + 64p).
    unsigned long long bias2[4];
#pragma unroll
    for (int p = 0; p < 4; ++p)
        bias2[p] = pack2(Bsm[p * 64 + lane * 2], Bsm[p * 64 + lane * 2 + 1]);

    for (int t = 0; t < TT; ++t) {
        // ---- stage inputs ----
        if (l == 0) {
            if (tid < 64) Asm[tid * 128 + 64] = x[(g * 64 + tid) * TT + t];
            __syncthreads();
        } else {
            if (tid == 0) {
                const int* fp = &g_flags[((l - 1) * TT + t) * 2 + g];
                int v;
                do {
                    asm volatile("ld.acquire.gpu.global.b32 %0, [%1];"
                                 : "=r"(v) : "l"(fp) : "memory");
                } while (v == 0);
            }
            __syncthreads();
            const float4* src = (const float4*)(g_hstage +
                ((size_t)((l - 1) * TT + t) * BB + g * 64) * HH);
#pragma unroll
            for (int r = 0; r < 4; ++r) {
                int idx = tid + r * 256;        // 1024 float4s = 64x64 floats
                float4 v = src[idx];
                int m  = idx >> 4;              // 16 float4 per 64-float row
                int k4 = idx & 15;
                *(float4*)&Asm[m * 128 + k4 * 4] = v;
            }
            __syncthreads();
        }

        // ---- GEMM: z[64][256] = A[64][K] @ W[K][256] + b ----
        unsigned long long acc[8][4];
#pragma unroll
        for (int i = 0; i < 8; ++i)
#pragma unroll
            for (int p = 0; p < 4; ++p) acc[i][p] = bias2[p];

        const float* Arow = Asm + m0 * 128;
#pragma unroll 4
        for (int k = 0; k < K; ++k) {
            const float* wr = Wsm + k * 256 + lane * 2;
            unsigned long long w0_ = *(const unsigned long long*)(wr);
            unsigned long long w1_ = *(const unsigned long long*)(wr + 64);
            unsigned long long w2_ = *(const unsigned long long*)(wr + 128);
            unsigned long long w3_ = *(const unsigned long long*)(wr + 192);
#pragma unroll
            for (int i = 0; i < 8; ++i) {
                float a = Arow[i * 128 + k];           // SMEM broadcast
                unsigned long long a2 = pack2(a, a);
                FMA2(acc[i][0], a2, w0_, acc[i][0]);
                FMA2(acc[i][1], a2, w1_, acc[i][1]);
                FMA2(acc[i][2], a2, w2_, acc[i][2]);
                FMA2(acc[i][3], a2, w3_, acc[i][3]);
            }
        }
        __syncthreads();   // all A reads done before h writes below

        // ---- gates: thread owns 2 h-units x 8 rows; pairs p = (i,j,f,o) ----
        float hx[8], hy[8];
#pragma unroll
        for (int i = 0; i < 8; ++i) {
            int m = m0 + i;
            float ix, iy, jx, jy, fx, fy, ox, oy;
            unpack2(acc[i][0], ix, iy);
            unpack2(acc[i][1], jx, jy);
            unpack2(acc[i][2], fx, fy);
            unpack2(acc[i][3], ox, oy);
            float2 c = *(float2*)&Csm[m * 64 + lane * 2];
            c.x = c.x * sigm(fx) + sigm(ix) * tanh_f(jx);
            c.y = c.y * sigm(fy) + sigm(iy) * tanh_f(jy);
            hx[i] = tanh_f(c.x) * sigm(ox);
            hy[i] = tanh_f(c.y) * sigm(oy);
            *(float2*)&Csm[m * 64 + lane * 2] = c;
            float2 h2 = make_float2(hx[i], hy[i]);
            *(float2*)&Asm[m * 128 + hcol + lane * 2] = h2;  // own h for t+1
        }

        if (l < 63) {
            // publish h to layer above, then release flag
            float* dst = g_hstage + ((size_t)(l * TT + t) * BB + g * 64) * HH;
#pragma unroll
            for (int i = 0; i < 8; ++i)
                *(float2*)&dst[(m0 + i) * 64 + lane * 2] = make_float2(hx[i], hy[i]);
            __threadfence();
            __syncthreads();
            if (tid == 0) {
                int* fp = &g_flags[(l * TT + t) * 2 + g];
                asm volatile("st.release.gpu.global.b32 [%0], %1;"
                             :: "l"(fp), "r"(1) : "memory");
            }
        } else {
            // dense head: pred[b,t] = relu(h . Wd[t] + bd[t])
            float wdx = __ldg(&Wd[t * 64 + lane * 2]);
            float wdy = __ldg(&Wd[t * 64 + lane * 2 + 1]);
            float bdt = __ldg(&bd[t]);
#pragma unroll
            for (int i = 0; i < 8; ++i) {
                float v = hx[i] * wdx + hy[i] * wdy;
#pragma unroll
                for (int off = 16; off; off >>= 1)
                    v += __shfl_xor_sync(0xffffffffu, v, off);
                if (lane == 0)
                    g_pred[(g * 64 + m0 + i) * TT + t] = fmaxf(v + bdt, 0.f);
            }
        }
    }
}

__global__ void reset_flags_kernel() {
    int i = blockIdx.x * blockDim.x + threadIdx.x;
    if (i < LL * TT * 2) g_flags[i] = 0;
}

__global__ void finish_kernel(const float* __restrict__ labels,
                              float* __restrict__ out, int out_size)
{
    __shared__ float red[256];
    int tid = threadIdx.x;
    bool write_pred = (out_size >= BB * TT);
    float s = 0.f;
    for (int i = tid; i < BB * TT; i += 256) {
        float p = g_pred[i];
        if (write_pred) out[i] = p;
        float d = labels[i] - p;
        s += d * d;
    }
    red[tid] = s;
    __syncthreads();
    for (int w = 128; w; w >>= 1) {
        if (tid < w) red[tid] += red[tid + w];
        __syncthreads();
    }
    if (tid == 0) {
        float loss = red[0] / (float)(BB * TT);
        if (out_size >= BB * TT + 1)      out[BB * TT] = loss;
        else if (out_size < BB * TT)      out[0] = loss;   // loss-only layout
    }
}

extern "C" void kernel_launch(void* const* d_in, const int* in_sizes, int n_in,
                              void* d_out, int out_size)
{
    const float* x      = (const float*)d_in[0];
    const float* labels = (const float*)d_in[1];
    const float* W0     = (const float*)d_in[2];
    const float* b0     = (const float*)d_in[3];
    const float* Wl     = (const float*)d_in[4];
    const float* bl     = (const float*)d_in[5];
    const float* Wd     = (const float*)d_in[6];
    const float* bd     = (const float*)d_in[7];
    float* out = (float*)d_out;

    size_t smem = (size_t)(128 * 256 + 64 * 128 + 64 * 64 + 256) * sizeof(float);
    cudaFuncSetAttribute(lstm_wave, cudaFuncAttributeMaxDynamicSharedMemorySize,
                         (int)smem);

    reset_flags_kernel<<<(LL * TT * 2 + 255) / 256, 256>>>();
    lstm_wave<<<LL * 2, 256, smem>>>(x, W0, b0, Wl, bl, Wd, bd);
    finish_kernel<<<1, 256>>>(labels, out, out_size);
}

// round 3
// speedup vs baseline: 1.0520x; 1.0001x over previous
#include <cuda_runtime.h>

// ---------------------------------------------------------------------------
// Stacked LSTM (T=64 timesteps, L=64 layers, B=128, H=64) + per-t dense head.
// Wavefront pipelining: 128 persistent CTAs = 64 layers x 2 batch-halves.
// CTA (l,g) owns batch rows [g*64, g*64+64) of layer l. Dependencies are
// neighbor-only (layer l needs layer l-1's h at same t), handled by
// acquire/release flags in global memory. Weights live in SMEM for all 64 t.
// GEMM: fp32 via packed fma.rn.f32x2 (2x FFMA throughput on sm_103a).
// ---------------------------------------------------------------------------

#define TT 64
#define LL 64
#define BB 128
#define HH 64

// Staging: h output of every (layer, t) cell. Written once per run per slot,
// so no anti-dependence hazards. 128 MB static (sanctioned scratch).
__device__ __align__(16) float g_hstage[(size_t)LL * TT * BB * HH];
__device__ int   g_flags[LL * TT * 2];
__device__ float g_pred[BB * TT];

__device__ __forceinline__ float sigm(float v)   { return 1.f / (1.f + __expf(-v)); }
__device__ __forceinline__ float tanh_f(float v) { return 1.f - 2.f / (__expf(2.f * v) + 1.f); }

__device__ __forceinline__ unsigned long long pack2(float x, float y) {
    unsigned long long r;
    asm("mov.b64 %0, {%1,%2};" : "=l"(r) : "f"(x), "f"(y));
    return r;
}
__device__ __forceinline__ void unpack2(unsigned long long v, float& x, float& y) {
    asm("mov.b64 {%0,%1}, %2;" : "=f"(x), "=f"(y) : "l"(v));
}
#define FMA2(d, a, b, c) \
    asm("fma.rn.f32x2 %0, %1, %2, %3;" : "=l"(d) : "l"(a), "l"(b), "l"(c))

__global__ void __launch_bounds__(256, 1) lstm_wave(
    const float* __restrict__ x,  const float* __restrict__ W0,
    const float* __restrict__ b0, const float* __restrict__ Wl,
    const float* __restrict__ bl, const float* __restrict__ Wd,
    const float* __restrict__ bd)
{
    extern __shared__ float smem[];
    float* Wsm = smem;                  // [128][256] weights (layer0: 65 rows)
    float* Asm = Wsm + 128 * 256;       // [64][128]  A = [h_below | h_own] (l>=1)
                                        //            or [h_own | x]        (l==0)
    float* Csm = Asm + 64 * 128;        // [64][64]   cell state
    float* Bsm = Csm + 64 * 64;         // [256]      bias

    const int bx   = blockIdx.x;
    const int l    = bx >> 1;
    const int g    = bx & 1;
    const int tid  = threadIdx.x;
    const int lane = tid & 31;          // n-group: columns lane*2 + 64p (p=gate)
    const int mg   = tid >> 5;          // warp = m-group
    const int m0   = mg << 3;           // 8 rows per warp

    const int K    = (l == 0) ? 65 : 128;
    const int hcol = (l == 0) ? 0  : 64;

    // ---- load weights + bias into SMEM (once) ----
    if (l == 0) {
        // Reorder: Wsm rows 0..63 = W0 rows 1..64 (h part), row 64 = W0 row 0 (x).
        for (int idx = tid; idx < 65 * 256; idx += 256) {
            int k = idx >> 8, n = idx & 255;
            int src = (k < 64) ? (k + 1) : 0;
            Wsm[idx] = W0[src * 256 + n];
        }
        Bsm[tid] = b0[tid];
    } else {
        const float4* Wg = (const float4*)(Wl + (size_t)(l - 1) * 128 * 256);
        float4* Wp = (float4*)Wsm;
        for (int idx = tid; idx < 128 * 256 / 4; idx += 256) Wp[idx] = Wg[idx];
        Bsm[tid] = bl[(l - 1) * 256 + tid];
    }
    for (int idx = tid; idx < 64 * 128; idx += 256) Asm[idx] = 0.f;
    for (int idx = tid; idx < 64 * 64;  idx += 256) Csm[idx] = 0.f;
    __syncthreads();

    // Pre-pack bias pairs for this thread's gate columns (n = lane*2 + 64p).
    unsigned long long bias2[4];
#pragma unroll
    for (int p = 0; p < 4; ++p)
        bias2[p] = pack2(Bsm[p * 64 + lane * 2], Bsm[p * 64 + lane * 2 + 1]);

    for (int t = 0; t < TT; ++t) {
        // ---- stage inputs ----
        if (l == 0) {
            if (tid < 64) Asm[tid * 128 + 64] = x[(g * 64 + tid) * TT + t];
            __syncthreads();
        } else {
            if (tid == 0) {
                const int* fp = &g_flags[((l - 1) * TT + t) * 2 + g];
                int v;
                do {
                    asm volatile("ld.acquire.gpu.global.b32 %0, [%1];"
                                 : "=r"(v) : "l"(fp) : "memory");
                } while (v == 0);
            }
            __syncthreads();
            const float4* src = (const float4*)(g_hstage +
                ((size_t)((l - 1) * TT + t) * BB + g * 64) * HH);
#pragma unroll
            for (int r = 0; r < 4; ++r) {
                int idx = tid + r * 256;        // 1024 float4s = 64x64 floats
                float4 v = src[idx];
                int m  = idx >> 4;              // 16 float4 per 64-float row
                int k4 = idx & 15;
                *(float4*)&Asm[m * 128 + k4 * 4] = v;
            }
            __syncthreads();
        }

        // ---- GEMM: z[64][256] = A[64][K] @ W[K][256] + b ----
        unsigned long long acc[8][4];
#pragma unroll
        for (int i = 0; i < 8; ++i)
#pragma unroll
            for (int p = 0; p < 4; ++p) acc[i][p] = bias2[p];

        const float* Arow = Asm + m0 * 128;
#pragma unroll 4
        for (int k = 0; k < K; ++k) {
            const float* wr = Wsm + k * 256 + lane * 2;
            unsigned long long w0_ = *(const unsigned long long*)(wr);
            unsigned long long w1_ = *(const unsigned long long*)(wr + 64);
            unsigned long long w2_ = *(const unsigned long long*)(wr + 128);
            unsigned long long w3_ = *(const unsigned long long*)(wr + 192);
#pragma unroll
            for (int i = 0; i < 8; ++i) {
                float a = Arow[i * 128 + k];           // SMEM broadcast
                unsigned long long a2 = pack2(a, a);
                FMA2(acc[i][0], a2, w0_, acc[i][0]);
                FMA2(acc[i][1], a2, w1_, acc[i][1]);
                FMA2(acc[i][2], a2, w2_, acc[i][2]);
                FMA2(acc[i][3], a2, w3_, acc[i][3]);
            }
        }
        __syncthreads();   // all A reads done before h writes below

        // ---- gates: thread owns 2 h-units x 8 rows; pairs p = (i,j,f,o) ----
        float hx[8], hy[8];
#pragma unroll
        for (int i = 0; i < 8; ++i) {
            int m = m0 + i;
            float ix, iy, jx, jy, fx, fy, ox, oy;
            unpack2(acc[i][0], ix, iy);
            unpack2(acc[i][1], jx, jy);
            unpack2(acc[i][2], fx, fy);
            unpack2(acc[i][3], ox, oy);
            float2 c = *(float2*)&Csm[m * 64 + lane * 2];
            c.x = c.x * sigm(fx) + sigm(ix) * tanh_f(jx);
            c.y = c.y * sigm(fy) + sigm(iy) * tanh_f(jy);
            hx[i] = tanh_f(c.x) * sigm(ox);
            hy[i] = tanh_f(c.y) * sigm(oy);
            *(float2*)&Csm[m * 64 + lane * 2] = c;
            float2 h2 = make_float2(hx[i], hy[i]);
            *(float2*)&Asm[m * 128 + hcol + lane * 2] = h2;  // own h for t+1
        }

        if (l < 63) {
            // publish h to layer above, then release flag
            float* dst = g_hstage + ((size_t)(l * TT + t) * BB + g * 64) * HH;
#pragma unroll
            for (int i = 0; i < 8; ++i)
                *(float2*)&dst[(m0 + i) * 64 + lane * 2] = make_float2(hx[i], hy[i]);
            __threadfence();
            __syncthreads();
            if (tid == 0) {
                int* fp = &g_flags[(l * TT + t) * 2 + g];
                asm volatile("st.release.gpu.global.b32 [%0], %1;"
                             :: "l"(fp), "r"(1) : "memory");
            }
        } else {
            // dense head: pred[b,t] = relu(h . Wd[t] + bd[t])
            float wdx = __ldg(&Wd[t * 64 + lane * 2]);
            float wdy = __ldg(&Wd[t * 64 + lane * 2 + 1]);
            float bdt = __ldg(&bd[t]);
#pragma unroll
            for (int i = 0; i < 8; ++i) {
                float v = hx[i] * wdx + hy[i] * wdy;
#pragma unroll
                for (int off = 16; off; off >>= 1)
                    v += __shfl_xor_sync(0xffffffffu, v, off);
                if (lane == 0)
                    g_pred[(g * 64 + m0 + i) * TT + t] = fmaxf(v + bdt, 0.f);
            }
        }
    }
}

__global__ void reset_flags_kernel() {
    int i = blockIdx.x * blockDim.x + threadIdx.x;
    if (i < LL * TT * 2) g_flags[i] = 0;
}

__global__ void finish_kernel(const float* __restrict__ labels,
                              float* __restrict__ out, int out_size)
{
    __shared__ float red[256];
    int tid = threadIdx.x;
    bool write_pred = (out_size >= BB * TT);
    float s = 0.f;
    for (int i = tid; i < BB * TT; i += 256) {
        float p = g_pred[i];
        if (write_pred) out[i] = p;
        float d = labels[i] - p;
        s += d * d;
    }
    red[tid] = s;
    __syncthreads();
    for (int w = 128; w; w >>= 1) {
        if (tid < w) red[tid] += red[tid + w];
        __syncthreads();
    }
    if (tid == 0) {
        float loss = red[0] / (float)(BB * TT);
        if (out_size >= BB * TT + 1)      out[BB * TT] = loss;
        else if (out_size < BB * TT)      out[0] = loss;   // loss-only layout
    }
}

extern "C" void kernel_launch(void* const* d_in, const int* in_sizes, int n_in,
                              void* d_out, int out_size)
{
    const float* x      = (const float*)d_in[0];
    const float* labels = (const float*)d_in[1];
    const float* W0     = (const float*)d_in[2];
    const float* b0     = (const float*)d_in[3];
    const float* Wl     = (const float*)d_in[4];
    const float* bl     = (const float*)d_in[5];
    const float* Wd     = (const float*)d_in[6];
    const float* bd     = (const float*)d_in[7];
    float* out = (float*)d_out;

    size_t smem = (size_t)(128 * 256 + 64 * 128 + 64 * 64 + 256) * sizeof(float);
    cudaFuncSetAttribute(lstm_wave, cudaFuncAttributeMaxDynamicSharedMemorySize,
                         (int)smem);

    reset_flags_kernel<<<(LL * TT * 2 + 255) / 256, 256>>>();
    lstm_wave<<<LL * 2, 256, smem>>>(x, W0, b0, Wl, bl, Wd, bd);
    finish_kernel<<<1, 256>>>(labels, out, out_size);
}

// round 4
// speedup vs baseline: 1.0534x; 1.0014x over previous
#include <cuda_runtime.h>

// ---------------------------------------------------------------------------
// Stacked LSTM (T=64 timesteps, L=64 layers, B=128, H=64) + per-t dense head.
// Wavefront pipelining: 128 persistent CTAs = 64 layers x 2 batch-halves.
// CTA (l,g) owns batch rows [g*64, g*64+64) of layer l. Dependencies are
// neighbor-only (layer l needs layer l-1's h at same t), handled by
// acquire/release flags in global memory. Weights live in SMEM for all 64 t.
// GEMM: fp32 via packed fma.rn.f32x2 (2x FFMA throughput on sm_103a).
// ---------------------------------------------------------------------------

#define TT 64
#define LL 64
#define BB 128
#define HH 64

// Staging: h output of every (layer, t) cell. Written once per run per slot,
// so no anti-dependence hazards. 128 MB static (sanctioned scratch).
__device__ __align__(16) float g_hstage[(size_t)LL * TT * BB * HH];
__device__ int   g_flags[LL * TT * 2];
__device__ float g_pred[BB * TT];

__device__ __forceinline__ float sigm(float v)   { return 1.f / (1.f + __expf(-v)); }
__device__ __forceinline__ float tanh_f(float v) { return 1.f - 2.f / (__expf(2.f * v) + 1.f); }

__device__ __forceinline__ unsigned long long pack2(float x, float y) {
    unsigned long long r;
    asm("mov.b64 %0, {%1,%2};" : "=l"(r) : "f"(x), "f"(y));
    return r;
}
__device__ __forceinline__ void unpack2(unsigned long long v, float& x, float& y) {
    asm("mov.b64 {%0,%1}, %2;" : "=f"(x), "=f"(y) : "l"(v));
}
#define FMA2(d, a, b, c) \
    asm("fma.rn.f32x2 %0, %1, %2, %3;" : "=l"(d) : "l"(a), "l"(b), "l"(c))

__global__ void __launch_bounds__(256, 1) lstm_wave(
    const float* __restrict__ x,  const float* __restrict__ W0,
    const float* __restrict__ b0, const float* __restrict__ Wl,
    const float* __restrict__ bl, const float* __restrict__ Wd,
    const float* __restrict__ bd)
{
    extern __shared__ float smem[];
    float* Wsm = smem;                  // [128][256] weights (layer0: 65 rows)
    float* Asm = Wsm + 128 * 256;       // [64][128]  A = [h_below | h_own] (l>=1)
                                        //            or [h_own | x]        (l==0)
    float* Csm = Asm + 64 * 128;        // [64][64]   cell state
    float* Bsm = Csm + 64 * 64;         // [256]      bias

    const int bx   = blockIdx.x;
    const int l    = bx >> 1;
    const int g    = bx & 1;
    const int tid  = threadIdx.x;
    const int lane = tid & 31;          // n-group: columns lane*2 + 64p (p=gate)
    const int mg   = tid >> 5;          // warp = m-group
    const int m0   = mg << 3;           // 8 rows per warp

    const int K    = (l == 0) ? 65 : 128;
    const int hcol = (l == 0) ? 0  : 64;

    // ---- load weights + bias into SMEM (once) ----
    if (l == 0) {
        // Reorder: Wsm rows 0..63 = W0 rows 1..64 (h part), row 64 = W0 row 0 (x).
        for (int idx = tid; idx < 65 * 256; idx += 256) {
            int k = idx >> 8, n = idx & 255;
            int src = (k < 64) ? (k + 1) : 0;
            Wsm[idx] = W0[src * 256 + n];
        }
        Bsm[tid] = b0[tid];
    } else {
        const float4* Wg = (const float4*)(Wl + (size_t)(l - 1) * 128 * 256);
        float4* Wp = (float4*)Wsm;
        for (int idx = tid; idx < 128 * 256 / 4; idx += 256) Wp[idx] = Wg[idx];
        Bsm[tid] = bl[(l - 1) * 256 + tid];
    }
    for (int idx = tid; idx < 64 * 128; idx += 256) Asm[idx] = 0.f;
    for (int idx = tid; idx < 64 * 64;  idx += 256) Csm[idx] = 0.f;
    __syncthreads();

    // Pre-pack bias pairs for this thread's gate columns (n = lane*2 + 64p).
    unsigned long long bias2[4];
#pragma unroll
    for (int p = 0; p < 4; ++p)
        bias2[p] = pack2(Bsm[p * 64 + lane * 2], Bsm[p * 64 + lane * 2 + 1]);

    for (int t = 0; t < TT; ++t) {
        // ---- stage inputs ----
        if (l == 0) {
            if (tid < 64) Asm[tid * 128 + 64] = x[(g * 64 + tid) * TT + t];
            __syncthreads();
        } else {
            if (tid == 0) {
                const int* fp = &g_flags[((l - 1) * TT + t) * 2 + g];
                int v;
                do {
                    asm volatile("ld.acquire.gpu.global.b32 %0, [%1];"
                                 : "=r"(v) : "l"(fp) : "memory");
                } while (v == 0);
            }
            __syncthreads();
            const float4* src = (const float4*)(g_hstage +
                ((size_t)((l - 1) * TT + t) * BB + g * 64) * HH);
#pragma unroll
            for (int r = 0; r < 4; ++r) {
                int idx = tid + r * 256;        // 1024 float4s = 64x64 floats
                float4 v = src[idx];
                int m  = idx >> 4;              // 16 float4 per 64-float row
                int k4 = idx & 15;
                *(float4*)&Asm[m * 128 + k4 * 4] = v;
            }
            __syncthreads();
        }

        // ---- GEMM: z[64][256] = A[64][K] @ W[K][256] + b ----
        unsigned long long acc[8][4];
#pragma unroll
        for (int i = 0; i < 8; ++i)
#pragma unroll
            for (int p = 0; p < 4; ++p) acc[i][p] = bias2[p];

        const float* Arow = Asm + m0 * 128;
#pragma unroll 4
        for (int k = 0; k < K; ++k) {
            const float* wr = Wsm + k * 256 + lane * 2;
            unsigned long long w0_ = *(const unsigned long long*)(wr);
            unsigned long long w1_ = *(const unsigned long long*)(wr + 64);
            unsigned long long w2_ = *(const unsigned long long*)(wr + 128);
            unsigned long long w3_ = *(const unsigned long long*)(wr + 192);
#pragma unroll
            for (int i = 0; i < 8; ++i) {
                float a = Arow[i * 128 + k];           // SMEM broadcast
                unsigned long long a2 = pack2(a, a);
                FMA2(acc[i][0], a2, w0_, acc[i][0]);
                FMA2(acc[i][1], a2, w1_, acc[i][1]);
                FMA2(acc[i][2], a2, w2_, acc[i][2]);
                FMA2(acc[i][3], a2, w3_, acc[i][3]);
            }
        }
        __syncthreads();   // all A reads done before h writes below

        // ---- gates: thread owns 2 h-units x 8 rows; pairs p = (i,j,f,o) ----
        float hx[8], hy[8];
#pragma unroll
        for (int i = 0; i < 8; ++i) {
            int m = m0 + i;
            float ix, iy, jx, jy, fx, fy, ox, oy;
            unpack2(acc[i][0], ix, iy);
            unpack2(acc[i][1], jx, jy);
            unpack2(acc[i][2], fx, fy);
            unpack2(acc[i][3], ox, oy);
            float2 c = *(float2*)&Csm[m * 64 + lane * 2];
            c.x = c.x * sigm(fx) + sigm(ix) * tanh_f(jx);
            c.y = c.y * sigm(fy) + sigm(iy) * tanh_f(jy);
            hx[i] = tanh_f(c.x) * sigm(ox);
            hy[i] = tanh_f(c.y) * sigm(oy);
            *(float2*)&Csm[m * 64 + lane * 2] = c;
            float2 h2 = make_float2(hx[i], hy[i]);
            *(float2*)&Asm[m * 128 + hcol + lane * 2] = h2;  // own h for t+1
        }

        if (l < 63) {
            // publish h to layer above, then release flag
            float* dst = g_hstage + ((size_t)(l * TT + t) * BB + g * 64) * HH;
#pragma unroll
            for (int i = 0; i < 8; ++i)
                *(float2*)&dst[(m0 + i) * 64 + lane * 2] = make_float2(hx[i], hy[i]);
            __threadfence();
            __syncthreads();
            if (tid == 0) {
                int* fp = &g_flags[(l * TT + t) * 2 + g];
                asm volatile("st.release.gpu.global.b32 [%0], %1;"
                             :: "l"(fp), "r"(1) : "memory");
            }
        } else {
            // dense head: pred[b,t] = relu(h . Wd[t] + bd[t])
            float wdx = __ldg(&Wd[t * 64 + lane * 2]);
            float wdy = __ldg(&Wd[t * 64 + lane * 2 + 1]);
            float bdt = __ldg(&bd[t]);
#pragma unroll
            for (int i = 0; i < 8; ++i) {
                float v = hx[i] * wdx + hy[i] * wdy;
#pragma unroll
                for (int off = 16; off; off >>= 1)
                    v += __shfl_xor_sync(0xffffffffu, v, off);
                if (lane == 0)
                    g_pred[(g * 64 + m0 + i) * TT + t] = fmaxf(v + bdt, 0.f);
            }
        }
    }
}

__global__ void reset_flags_kernel() {
    int i = blockIdx.x * blockDim.x + threadIdx.x;
    if (i < LL * TT * 2) g_flags[i] = 0;
}

__global__ void finish_kernel(const float* __restrict__ labels,
                              float* __restrict__ out, int out_size)
{
    __shared__ float red[256];
    int tid = threadIdx.x;
    bool write_pred = (out_size >= BB * TT);
    float s = 0.f;
    for (int i = tid; i < BB * TT; i += 256) {
        float p = g_pred[i];
        if (write_pred) out[i] = p;
        float d = labels[i] - p;
        s += d * d;
    }
    red[tid] = s;
    __syncthreads();
    for (int w = 128; w; w >>= 1) {
        if (tid < w) red[tid] += red[tid + w];
        __syncthreads();
    }
    if (tid == 0) {
        float loss = red[0] / (float)(BB * TT);
        if (out_size >= BB * TT + 1)      out[BB * TT] = loss;
        else if (out_size < BB * TT)      out[0] = loss;   // loss-only layout
    }
}

extern "C" void kernel_launch(void* const* d_in, const int* in_sizes, int n_in,
                              void* d_out, int out_size)
{
    const float* x      = (const float*)d_in[0];
    const float* labels = (const float*)d_in[1];
    const float* W0     = (const float*)d_in[2];
    const float* b0     = (const float*)d_in[3];
    const float* Wl     = (const float*)d_in[4];
    const float* bl     = (const float*)d_in[5];
    const float* Wd     = (const float*)d_in[6];
    const float* bd     = (const float*)d_in[7];
    float* out = (float*)d_out;

    size_t smem = (size_t)(128 * 256 + 64 * 128 + 64 * 64 + 256) * sizeof(float);
    cudaFuncSetAttribute(lstm_wave, cudaFuncAttributeMaxDynamicSharedMemorySize,
                         (int)smem);

    reset_flags_kernel<<<(LL * TT * 2 + 255) / 256, 256>>>();
    lstm_wave<<<LL * 2, 256, smem>>>(x, W0, b0, Wl, bl, Wd, bd);
    finish_kernel<<<1, 256>>>(labels, out, out_size);
}